// round 1
// baseline (speedup 1.0000x reference)
#include <cuda_runtime.h>

#define BATCH 64
#define PLEN  128
#define DIM   1024
#define ROWS  (BATCH * PLEN)

// Scratch: per-row attention score s and fc projection t.
__device__ float g_s[ROWS];
__device__ float g_t[ROWS];

// Kernel 1: one block per (b,p) row. Each block computes
//   s = dot(concat(h_row, q_row), W_att)
//   t = dot(concat(h_row, q_row), W_fc)
// 256 threads * float4 = 1024 floats => exactly one D-length vector per tensor.
__global__ void __launch_bounds__(256)
score_kernel(const float* __restrict__ h,
             const float* __restrict__ q,
             const float* __restrict__ W_att,
             const float* __restrict__ W_fc) {
    const int row = blockIdx.x;          // b*PLEN + p
    const int tid = threadIdx.x;         // 0..255

    const float4* h4   = reinterpret_cast<const float4*>(h + (size_t)row * DIM);
    const float4* q4   = reinterpret_cast<const float4*>(q + (size_t)row * DIM);
    const float4* wa_h = reinterpret_cast<const float4*>(W_att);
    const float4* wa_q = reinterpret_cast<const float4*>(W_att + DIM);
    const float4* wf_h = reinterpret_cast<const float4*>(W_fc);
    const float4* wf_q = reinterpret_cast<const float4*>(W_fc + DIM);

    const float4 hv  = h4[tid];
    const float4 qv  = q4[tid];
    const float4 wah = wa_h[tid];
    const float4 waq = wa_q[tid];
    const float4 wfh = wf_h[tid];
    const float4 wfq = wf_q[tid];

    float s = hv.x * wah.x + hv.y * wah.y + hv.z * wah.z + hv.w * wah.w
            + qv.x * waq.x + qv.y * waq.y + qv.z * waq.z + qv.w * waq.w;
    float t = hv.x * wfh.x + hv.y * wfh.y + hv.z * wfh.z + hv.w * wfh.w
            + qv.x * wfq.x + qv.y * wfq.y + qv.z * wfq.z + qv.w * wfq.w;

    // warp reduce both values
    #pragma unroll
    for (int off = 16; off > 0; off >>= 1) {
        s += __shfl_xor_sync(0xffffffffu, s, off);
        t += __shfl_xor_sync(0xffffffffu, t, off);
    }

    __shared__ float ss[8];
    __shared__ float st[8];
    const int warp = tid >> 5;
    const int lane = tid & 31;
    if (lane == 0) { ss[warp] = s; st[warp] = t; }
    __syncthreads();
    if (tid == 0) {
        float S = 0.f, T = 0.f;
        #pragma unroll
        for (int w = 0; w < 8; ++w) { S += ss[w]; T += st[w]; }
        g_s[row] = S;
        g_t[row] = T;
    }
}

// Kernel 2: one block per batch. Softmax over PLEN scores, weighted sum of t.
__global__ void __launch_bounds__(PLEN)
softmax_pool_kernel(const float* __restrict__ b_att,
                    const float* __restrict__ b_fc,
                    float* __restrict__ out) {
    const int b = blockIdx.x;
    const int p = threadIdx.x;

    const float s = g_s[b * PLEN + p] + b_att[0];
    const float t = g_t[b * PLEN + p];

    const int warp = p >> 5;
    const int lane = p & 31;

    __shared__ float red[4];

    // block max
    float m = s;
    #pragma unroll
    for (int off = 16; off > 0; off >>= 1)
        m = fmaxf(m, __shfl_xor_sync(0xffffffffu, m, off));
    if (lane == 0) red[warp] = m;
    __syncthreads();
    const float bmax = fmaxf(fmaxf(red[0], red[1]), fmaxf(red[2], red[3]));
    __syncthreads();

    const float e = expf(s - bmax);
    float num = e * t;
    float den = e;
    #pragma unroll
    for (int off = 16; off > 0; off >>= 1) {
        num += __shfl_xor_sync(0xffffffffu, num, off);
        den += __shfl_xor_sync(0xffffffffu, den, off);
    }

    __shared__ float rn[4];
    __shared__ float rd[4];
    if (lane == 0) { rn[warp] = num; rd[warp] = den; }
    __syncthreads();
    if (p == 0) {
        const float N = rn[0] + rn[1] + rn[2] + rn[3];
        const float De = rd[0] + rd[1] + rd[2] + rd[3];
        out[b] = N / De + b_fc[0];
    }
}

extern "C" void kernel_launch(void* const* d_in, const int* in_sizes, int n_in,
                              void* d_out, int out_size) {
    const float* h     = (const float*)d_in[0];
    const float* q     = (const float*)d_in[1];
    const float* W_att = (const float*)d_in[2];
    const float* b_att = (const float*)d_in[3];
    const float* W_fc  = (const float*)d_in[4];
    const float* b_fc  = (const float*)d_in[5];
    float* out = (float*)d_out;

    score_kernel<<<ROWS, 256>>>(h, q, W_att, W_fc);
    softmax_pool_kernel<<<BATCH, PLEN>>>(b_att, b_fc, out);
}